// round 14
// baseline (speedup 1.0000x reference)
#include <cuda_runtime.h>

// ---------------------------------------------------------------------------
// Grid-accelerated exact NN (chamfer forward, masked mean).
// R9-proven setup (zero / count / 3-phase scan / scatter) + new search:
//   one WARP per pc0 point. Phase 1: flat 5x5x5 box scan (25 straight-line
//   row-runs, no bit-iteration) certifying ~90% of points at (2H)^2.
//   Phase 2 (tails): shell expansion r=3..12 with occupancy bitmasks.
// Final reduction fused into search via done-counter (last block reduces).
// ---------------------------------------------------------------------------

#define NPTS 65536
#define GD   64
#define NC   (GD * GD * GD)
#define H    0.125f
#define INVH 8.0f
#define GOFF 4.0f
#define ST   256                     // 8 warps per block
#define SB   (NPTS * 32 / ST)        // 8192 blocks: one warp per point

typedef unsigned long long u64;

// Scratch (no allocations -> __device__ globals)
__device__ int    g_count [NC];      // pc1 grid
__device__ int    g_off   [NC + 1];
__device__ int    g_cursor[NC];
__device__ int    g_count0 [NC];     // pc0 grid
__device__ int    g_off0   [NC + 1];
__device__ int    g_cursor0[NC];
__device__ int    g_bsum  [2][256];
__device__ u64    g_occ [GD * GD];   // per (z,y) row: occupied x bits (pc1)
__device__ u64    g_occX[GD * GD];   // per (z,x) column: occupied y bits (pc1)
__device__ u64    g_occP[GD];        // per z plane: nonempty-row y bits
__device__ float4 g_pts [NPTS];      // sorted pc1: (x,y,z,||b||^2)
__device__ float4 g_pts0[NPTS];      // sorted pc0: (x,y,z,||a||^2)
__device__ float  g_block[SB * 2];   // per-block (sum, count)
__device__ int    g_done;            // search completion counter

__device__ __forceinline__ int cellc(float v) {
    int c = (int)floorf((v + GOFF) * INVH);
    return min(GD - 1, max(0, c));
}
__device__ __forceinline__ u64 bitrange(int lo, int hi) {
    return (~0ull << lo) & (~0ull >> (63 - hi));
}

// ---------------------------------------------------------------------------
__global__ void zero_k() {
    int i = blockIdx.x * blockDim.x + threadIdx.x;
    if (i < NC) { g_count[i] = 0; g_count0[i] = 0; }
    if (i < GD * GD) { g_occ[i] = 0; g_occX[i] = 0; }
    if (i < GD) g_occP[i] = 0;
    if (i == 0) g_done = 0;
}

__global__ void count_k(const float* __restrict__ pc1,
                        const float* __restrict__ pc0) {
    int i = blockIdx.x * blockDim.x + threadIdx.x;
    {
        float x = pc1[3 * i], y = pc1[3 * i + 1], z = pc1[3 * i + 2];
        int cx = cellc(x), cy = cellc(y), cz = cellc(z);
        atomicAdd(&g_count[(cz * GD + cy) * GD + cx], 1);
        atomicOr(&g_occ [cz * GD + cy], 1ull << cx);
        atomicOr(&g_occX[cz * GD + cx], 1ull << cy);
    }
    {
        float x = pc0[3 * i], y = pc0[3 * i + 1], z = pc0[3 * i + 2];
        atomicAdd(&g_count0[(cellc(z) * GD + cellc(y)) * GD + cellc(x)], 1);
    }
}

// --- 3-phase exclusive scan, both grids via grid.y / grid.x (R9-proven) ---
__global__ void scan_a() {
    int which = blockIdx.y;
    int* cnt = which ? g_count0 : g_count;
    int t = threadIdx.x;
    int base = (blockIdx.x * 256 + t) * 4;
    int s = cnt[base] + cnt[base + 1] + cnt[base + 2] + cnt[base + 3];
    __shared__ int sh[256];
    sh[t] = s; __syncthreads();
    for (int o = 1; o < 256; o <<= 1) {
        int u = (t >= o) ? sh[t - o] : 0; __syncthreads();
        sh[t] += u; __syncthreads();
    }
    if (t == 255) g_bsum[which][blockIdx.x] = sh[255];
}

// blocks 0,1: block-sum scans; block 2: build g_occP from g_occ
__global__ void scan_b() {
    int t = threadIdx.x;
    if (blockIdx.x == 2) {
        int z = t >> 2, q = t & 3;
        u64 w = 0;
        for (int y = q * 16; y < q * 16 + 16; y++)
            if (g_occ[z * GD + y]) w |= 1ull << y;
        if (w) atomicOr(&g_occP[z], w);
        return;
    }
    int which = blockIdx.x;
    __shared__ int sh[256];
    int v = g_bsum[which][t];
    sh[t] = v; __syncthreads();
    for (int o = 1; o < 256; o <<= 1) {
        int u = (t >= o) ? sh[t - o] : 0; __syncthreads();
        sh[t] += u; __syncthreads();
    }
    g_bsum[which][t] = sh[t] - v;
}

__global__ void scan_c() {
    int which = blockIdx.y;
    int* cnt = which ? g_count0  : g_count;
    int* off = which ? g_off0    : g_off;
    int* cur = which ? g_cursor0 : g_cursor;
    int t = threadIdx.x;
    int base = (blockIdx.x * 256 + t) * 4;
    int c0 = cnt[base], c1 = cnt[base + 1];
    int c2 = cnt[base + 2], c3 = cnt[base + 3];
    int s = c0 + c1 + c2 + c3;
    __shared__ int sh[256];
    sh[t] = s; __syncthreads();
    for (int o = 1; o < 256; o <<= 1) {
        int u = (t >= o) ? sh[t - o] : 0; __syncthreads();
        sh[t] += u; __syncthreads();
    }
    int o0 = sh[t] - s + g_bsum[which][blockIdx.x];
    int o1 = o0 + c0, o2 = o1 + c1, o3 = o2 + c2;
    off[base] = o0;     off[base + 1] = o1;
    off[base + 2] = o2; off[base + 3] = o3;
    cur[base] = o0;     cur[base + 1] = o1;
    cur[base + 2] = o2; cur[base + 3] = o3;
    if (blockIdx.x == 0 && t == 0) off[NC] = NPTS;
}

__global__ void scatter_k(const float* __restrict__ pc1,
                          const float* __restrict__ pc0) {
    int i = blockIdx.x * blockDim.x + threadIdx.x;
    {
        float x = pc1[3 * i], y = pc1[3 * i + 1], z = pc1[3 * i + 2];
        int c = (cellc(z) * GD + cellc(y)) * GD + cellc(x);
        int idx = atomicAdd(&g_cursor[c], 1);
        g_pts[idx] = make_float4(x, y, z, x * x + y * y + z * z);
    }
    {
        float x = pc0[3 * i], y = pc0[3 * i + 1], z = pc0[3 * i + 2];
        int c = (cellc(z) * GD + cellc(y)) * GD + cellc(x);
        int idx = atomicAdd(&g_cursor0[c], 1);
        g_pts0[idx] = make_float4(x, y, z, fmaf(x, x, fmaf(y, y, z * z)));
    }
}

// ---------------------------------------------------------------------------
// Search: ONE WARP per sorted pc0 point (uniform traversal, no intra-warp
// divergence across points). Phase 1: flat r<=2 box, 25 row-runs. Phase 2
// (uncertified tails): shells r=3..12 with occP/occ/occX bitmasks.
// cur = min of ||b||^2 - 2 a.b; full d = cur + ||a||^2 (validated chain).
// ---------------------------------------------------------------------------
__global__ void __launch_bounds__(ST) search_k(float* __restrict__ out) {
    int t = threadIdx.x;
    int l = t & 31;
    int i = blockIdx.x * (ST / 32) + (t >> 5);   // one point per warp

    float4 a = __ldg(&g_pts0[i]);
    float nax = -2.f * a.x, nay = -2.f * a.y, naz = -2.f * a.z;
    float asq = a.w;
    int cx = cellc(a.x), cy = cellc(a.y), cz = cellc(a.z);

    float c0a = 1e30f;

    auto scan_run = [&](int cc0, int cc1) {
        int s = __ldg(&g_off[cc0]);              // uniform in warp -> broadcast
        int e = __ldg(&g_off[cc1 + 1]);
        for (int k = s + l; k < e; k += 32) {
            float4 p = __ldg(&g_pts[k]);
            c0a = fminf(c0a, fmaf(nax, p.x, fmaf(nay, p.y, fmaf(naz, p.z, p.w))));
        }
    };
    auto warp_min = [&](float v) {
        v = fminf(v, __shfl_xor_sync(0xFFFFFFFFu, v, 1));
        v = fminf(v, __shfl_xor_sync(0xFFFFFFFFu, v, 2));
        v = fminf(v, __shfl_xor_sync(0xFFFFFFFFu, v, 4));
        v = fminf(v, __shfl_xor_sync(0xFFFFFFFFu, v, 8));
        v = fminf(v, __shfl_xor_sync(0xFFFFFFFFu, v, 16));
        return v;
    };

    // ---- Phase 1: flat box r<=2 (superset of shells 0..2) ----
    {
        int z0 = max(cz - 2, 0), z1 = min(cz + 2, GD - 1);
        int y0 = max(cy - 2, 0), y1 = min(cy + 2, GD - 1);
        int x0 = max(cx - 2, 0), x1 = min(cx + 2, GD - 1);
        u64 xm = bitrange(x0, x1);
        for (int z = z0; z <= z1; z++) {
            int zb = z * GD;
#pragma unroll
            for (int y = y0; y <= y1; y++) {
                u64 w = __ldg(&g_occ[zb + y]) & xm;
                if (w) {
                    int lo = __ffsll((long long)w) - 1;
                    int hi = 63 - __clzll(w);
                    scan_run((zb + y) * GD + lo, (zb + y) * GD + hi);
                }
            }
        }
    }
    float m = warp_min(c0a);

    // ---- Phase 2: shells r=3..12 for uncertified tails ----
    if (!(m + asq <= 0.0625f)) {                 // (2H)^2: unscanned d >= this
        for (int r = 3; r <= 12; r++) {
            int z0 = max(cz - r, 0), z1 = min(cz + r, GD - 1);
            int y0 = max(cy - r, 0), y1 = min(cy + r, GD - 1);
            int xl = cx - r, xr = cx + r;
            int x0 = max(xl, 0), x1 = min(xr, GD - 1);
            u64 xm = bitrange(x0, x1);

            for (int z = z0; z <= z1; z++) {
                int zb = z * GD;
                bool zedge = (z == cz - r) || (z == cz + r);
                if (zedge) {
                    u64 wp = __ldg(&g_occP[z]) & bitrange(y0, y1);
                    while (wp) {
                        int y = __ffsll((long long)wp) - 1; wp &= wp - 1;
                        u64 w = __ldg(&g_occ[zb + y]) & xm;
                        if (w) {
                            int lo = __ffsll((long long)w) - 1;
                            int hi = 63 - __clzll(w);
                            scan_run((zb + y) * GD + lo, (zb + y) * GD + hi);
                        }
                    }
                } else {
                    int yl = cy - r, yr2 = cy + r;
                    if (yl >= 0) {
                        u64 w = __ldg(&g_occ[zb + yl]) & xm;
                        if (w) {
                            int lo = __ffsll((long long)w) - 1;
                            int hi = 63 - __clzll(w);
                            scan_run((zb + yl) * GD + lo, (zb + yl) * GD + hi);
                        }
                    }
                    if (yr2 <= GD - 1) {
                        u64 w = __ldg(&g_occ[zb + yr2]) & xm;
                        if (w) {
                            int lo = __ffsll((long long)w) - 1;
                            int hi = 63 - __clzll(w);
                            scan_run((zb + yr2) * GD + lo, (zb + yr2) * GD + hi);
                        }
                    }
                    int yi0 = max(yl + 1, 0), yi1 = min(yr2 - 1, GD - 1);
                    if (yi0 <= yi1) {
                        u64 ym = bitrange(yi0, yi1);
                        if (xl >= 0) {
                            u64 wc = __ldg(&g_occX[zb + xl]) & ym;
                            while (wc) {
                                int y = __ffsll((long long)wc) - 1; wc &= wc - 1;
                                int c = (zb + y) * GD + xl;
                                scan_run(c, c);
                            }
                        }
                        if (xr <= GD - 1) {
                            u64 wc = __ldg(&g_occX[zb + xr]) & ym;
                            while (wc) {
                                int y = __ffsll((long long)wc) - 1; wc &= wc - 1;
                                int c = (zb + y) * GD + xr;
                                scan_run(c, c);
                            }
                        }
                    }
                }
            }
            m = warp_min(c0a);
            float rh = r * H;
            float rh2 = rh * rh;
            if (m + asq <= rh2 || rh2 > 2.0f) break;   // unscanned have d >= rh2
        }
    }

    float d = m + asq;
    float s = 0.f, c = 0.f;
    if (l == 0 && d <= 2.0f) { s = d; c = 1.f; }   // one lane per point counts

    __shared__ float ss[ST], sc[ST];
    ss[t] = s; sc[t] = c;
    __syncthreads();
    for (int o = ST / 2; o > 0; o >>= 1) {
        if (t < o) { ss[t] += ss[t + o]; sc[t] += sc[t + o]; }
        __syncthreads();
    }
    __shared__ int isLast;
    if (t == 0) {
        g_block[2 * blockIdx.x + 0] = ss[0];
        g_block[2 * blockIdx.x + 1] = sc[0];
        __threadfence();
        isLast = (atomicAdd(&g_done, 1) == SB - 1);
    }
    __syncthreads();
    if (isLast) {
        // deterministic fixed-order final reduction by the last block
        float fs = 0.f, fc = 0.f;
        for (int k = t; k < SB; k += ST) {
            fs += g_block[2 * k + 0];
            fc += g_block[2 * k + 1];
        }
        ss[t] = fs; sc[t] = fc;
        __syncthreads();
        for (int o = ST / 2; o > 0; o >>= 1) {
            if (t < o) { ss[t] += ss[t + o]; sc[t] += sc[t + o]; }
            __syncthreads();
        }
        if (t == 0) out[0] = ss[0] / sc[0];
    }
}

extern "C" void kernel_launch(void* const* d_in, const int* in_sizes, int n_in,
                              void* d_out, int out_size) {
    const float* pc0 = (const float*)d_in[0];
    const float* pc1 = (const float*)d_in[1];
    (void)in_sizes; (void)n_in; (void)out_size;

    zero_k   <<<NC / 256, 256>>>();
    count_k  <<<NPTS / 256, 256>>>(pc1, pc0);
    scan_a   <<<dim3(256, 2), 256>>>();
    scan_b   <<<3, 256>>>();
    scan_c   <<<dim3(256, 2), 256>>>();
    scatter_k<<<NPTS / 256, 256>>>(pc1, pc0);
    search_k <<<SB, ST>>>((float*)d_out);
}

// round 15
// speedup vs baseline: 2.1511x; 2.1511x over previous
#include <cuda_runtime.h>

// ---------------------------------------------------------------------------
// Grid-accelerated exact NN (chamfer forward, masked mean).
// R9-proven setup + R9 search structure (8 lanes/point), with:
//   - phase 1: flat 3x3x3 box (9 masked row-runs; same cells as shells 0-1,
//     certify at h^2) replacing the bitmask-heavy shell code for ~88% of pts
//   - phase 2: shells r=2..12 (verbatim R9) for tails
//   - final reduction fused into search via done-counter
// ---------------------------------------------------------------------------

#define NPTS 65536
#define GD   64
#define NC   (GD * GD * GD)
#define H    0.125f
#define INVH 8.0f
#define GOFF 4.0f
#define ST   128
#define W    8                       // lanes per point
#define SB   (NPTS * W / ST)         // 4096 search blocks

typedef unsigned long long u64;

// Scratch (no allocations -> __device__ globals)
__device__ int    g_count [NC];      // pc1 grid
__device__ int    g_off   [NC + 1];
__device__ int    g_cursor[NC];
__device__ int    g_count0 [NC];     // pc0 grid
__device__ int    g_off0   [NC + 1];
__device__ int    g_cursor0[NC];
__device__ int    g_bsum  [2][256];
__device__ u64    g_occ [GD * GD];   // per (z,y) row: occupied x bits (pc1)
__device__ u64    g_occX[GD * GD];   // per (z,x) column: occupied y bits (pc1)
__device__ u64    g_occP[GD];        // per z plane: nonempty-row y bits
__device__ float4 g_pts [NPTS];      // sorted pc1: (x,y,z,||b||^2)
__device__ float4 g_pts0[NPTS];      // sorted pc0: (x,y,z,||a||^2)
__device__ float  g_block[SB * 2];   // per-block (sum, count)
__device__ int    g_done;            // search completion counter

__device__ __forceinline__ int cellc(float v) {
    int c = (int)floorf((v + GOFF) * INVH);
    return min(GD - 1, max(0, c));
}
__device__ __forceinline__ u64 bitrange(int lo, int hi) {
    return (~0ull << lo) & (~0ull >> (63 - hi));
}

// ---------------------------------------------------------------------------
__global__ void zero_k() {
    int i = blockIdx.x * blockDim.x + threadIdx.x;
    if (i < NC) { g_count[i] = 0; g_count0[i] = 0; }
    if (i < GD * GD) { g_occ[i] = 0; g_occX[i] = 0; }
    if (i < GD) g_occP[i] = 0;
    if (i == 0) g_done = 0;
}

__global__ void count_k(const float* __restrict__ pc1,
                        const float* __restrict__ pc0) {
    int i = blockIdx.x * blockDim.x + threadIdx.x;
    {
        float x = pc1[3 * i], y = pc1[3 * i + 1], z = pc1[3 * i + 2];
        int cx = cellc(x), cy = cellc(y), cz = cellc(z);
        atomicAdd(&g_count[(cz * GD + cy) * GD + cx], 1);
        atomicOr(&g_occ [cz * GD + cy], 1ull << cx);
        atomicOr(&g_occX[cz * GD + cx], 1ull << cy);
    }
    {
        float x = pc0[3 * i], y = pc0[3 * i + 1], z = pc0[3 * i + 2];
        atomicAdd(&g_count0[(cellc(z) * GD + cellc(y)) * GD + cellc(x)], 1);
    }
}

// --- 3-phase exclusive scan, both grids via grid.y / grid.x ---
__global__ void scan_a() {
    int which = blockIdx.y;
    int* cnt = which ? g_count0 : g_count;
    int t = threadIdx.x;
    int base = (blockIdx.x * 256 + t) * 4;
    int s = cnt[base] + cnt[base + 1] + cnt[base + 2] + cnt[base + 3];
    __shared__ int sh[256];
    sh[t] = s; __syncthreads();
    for (int o = 1; o < 256; o <<= 1) {
        int u = (t >= o) ? sh[t - o] : 0; __syncthreads();
        sh[t] += u; __syncthreads();
    }
    if (t == 255) g_bsum[which][blockIdx.x] = sh[255];
}

// blocks 0,1: block-sum scans; block 2: build g_occP from g_occ
__global__ void scan_b() {
    int t = threadIdx.x;
    if (blockIdx.x == 2) {
        int z = t >> 2, q = t & 3;
        u64 w = 0;
        for (int y = q * 16; y < q * 16 + 16; y++)
            if (g_occ[z * GD + y]) w |= 1ull << y;
        if (w) atomicOr(&g_occP[z], w);
        return;
    }
    int which = blockIdx.x;
    __shared__ int sh[256];
    int v = g_bsum[which][t];
    sh[t] = v; __syncthreads();
    for (int o = 1; o < 256; o <<= 1) {
        int u = (t >= o) ? sh[t - o] : 0; __syncthreads();
        sh[t] += u; __syncthreads();
    }
    g_bsum[which][t] = sh[t] - v;
}

__global__ void scan_c() {
    int which = blockIdx.y;
    int* cnt = which ? g_count0  : g_count;
    int* off = which ? g_off0    : g_off;
    int* cur = which ? g_cursor0 : g_cursor;
    int t = threadIdx.x;
    int base = (blockIdx.x * 256 + t) * 4;
    int c0 = cnt[base], c1 = cnt[base + 1];
    int c2 = cnt[base + 2], c3 = cnt[base + 3];
    int s = c0 + c1 + c2 + c3;
    __shared__ int sh[256];
    sh[t] = s; __syncthreads();
    for (int o = 1; o < 256; o <<= 1) {
        int u = (t >= o) ? sh[t - o] : 0; __syncthreads();
        sh[t] += u; __syncthreads();
    }
    int o0 = sh[t] - s + g_bsum[which][blockIdx.x];
    int o1 = o0 + c0, o2 = o1 + c1, o3 = o2 + c2;
    off[base] = o0;     off[base + 1] = o1;
    off[base + 2] = o2; off[base + 3] = o3;
    cur[base] = o0;     cur[base + 1] = o1;
    cur[base + 2] = o2; cur[base + 3] = o3;
    if (blockIdx.x == 0 && t == 0) off[NC] = NPTS;
}

__global__ void scatter_k(const float* __restrict__ pc1,
                          const float* __restrict__ pc0) {
    int i = blockIdx.x * blockDim.x + threadIdx.x;
    {
        float x = pc1[3 * i], y = pc1[3 * i + 1], z = pc1[3 * i + 2];
        int c = (cellc(z) * GD + cellc(y)) * GD + cellc(x);
        int idx = atomicAdd(&g_cursor[c], 1);
        g_pts[idx] = make_float4(x, y, z, x * x + y * y + z * z);
    }
    {
        float x = pc0[3 * i], y = pc0[3 * i + 1], z = pc0[3 * i + 2];
        int c = (cellc(z) * GD + cellc(y)) * GD + cellc(x);
        int idx = atomicAdd(&g_cursor0[c], 1);
        g_pts0[idx] = make_float4(x, y, z, fmaf(x, x, fmaf(y, y, z * z)));
    }
}

// ---------------------------------------------------------------------------
// Search: 8 lanes per sorted pc0 point (R9 structure). Phase 1: flat 3x3x3
// box (9 masked row-runs; covers shells 0-1; certify at h^2). Phase 2:
// shells r=2..12 with occP/occ/occX bitmasks (R9 verbatim). Last finishing
// block performs the deterministic fixed-order final reduction.
// ---------------------------------------------------------------------------
__global__ void __launch_bounds__(ST) search_k(float* __restrict__ out) {
    int t = threadIdx.x;
    int gid = blockIdx.x * ST + t;
    int i = gid / W;                         // point index
    int l = gid & (W - 1);                   // lane within group
    unsigned gm = 0xFFu << ((t & 31) & ~(W - 1));  // group-local shuffle mask

    float4 a = __ldg(&g_pts0[i]);
    float nax = -2.f * a.x, nay = -2.f * a.y, naz = -2.f * a.z;
    float asq = a.w;
    int cx = cellc(a.x), cy = cellc(a.y), cz = cellc(a.z);

    float c0a = 1e30f, c1a = 1e30f;

    auto scan_run = [&](int cc0, int cc1) {
        int s = __ldg(&g_off[cc0]);          // uniform in group -> broadcast
        int e = __ldg(&g_off[cc1 + 1]);
        int k = s + l;
        for (; k + W < e; k += 2 * W) {
            float4 p0 = __ldg(&g_pts[k]);
            float4 p1 = __ldg(&g_pts[k + W]);
            c0a = fminf(c0a, fmaf(nax, p0.x, fmaf(nay, p0.y, fmaf(naz, p0.z, p0.w))));
            c1a = fminf(c1a, fmaf(nax, p1.x, fmaf(nay, p1.y, fmaf(naz, p1.z, p1.w))));
        }
        if (k < e) {
            float4 p = __ldg(&g_pts[k]);
            c0a = fminf(c0a, fmaf(nax, p.x, fmaf(nay, p.y, fmaf(naz, p.z, p.w))));
        }
    };
    auto group_min = [&]() {
        float ml = fminf(c0a, c1a);
        ml = fminf(ml, __shfl_xor_sync(gm, ml, 1));
        ml = fminf(ml, __shfl_xor_sync(gm, ml, 2));
        ml = fminf(ml, __shfl_xor_sync(gm, ml, 4));
        return ml;
    };

    // ---- Phase 1: flat 3x3x3 box (shells 0-1), 9 masked row-runs ----
    {
        int z0 = max(cz - 1, 0), z1 = min(cz + 1, GD - 1);
        int y0 = max(cy - 1, 0), y1 = min(cy + 1, GD - 1);
        int x0 = max(cx - 1, 0), x1 = min(cx + 1, GD - 1);
        u64 xm = bitrange(x0, x1);
        for (int z = z0; z <= z1; z++) {
            int zb = z * GD;
            for (int y = y0; y <= y1; y++) {
                u64 w = __ldg(&g_occ[zb + y]) & xm;
                if (w) {
                    int lo = __ffsll((long long)w) - 1;
                    int hi = 63 - __clzll(w);
                    scan_run((zb + y) * GD + lo, (zb + y) * GD + hi);
                }
            }
        }
    }
    float m = group_min();

    // ---- Phase 2: shells r=2..12 for uncertified tails (R9 verbatim) ----
    if (!(m + asq <= H * H)) {               // unscanned have d >= h^2
        for (int r = 2; r <= 12; r++) {
            int z0 = max(cz - r, 0), z1 = min(cz + r, GD - 1);
            int y0 = max(cy - r, 0), y1 = min(cy + r, GD - 1);
            int xl = cx - r, xr = cx + r;
            int x0 = max(xl, 0), x1 = min(xr, GD - 1);
            u64 xm = bitrange(x0, x1);

            for (int z = z0; z <= z1; z++) {
                int zb = z * GD;
                bool zedge = (z == cz - r) || (z == cz + r);
                if (zedge) {
                    u64 wp = __ldg(&g_occP[z]) & bitrange(y0, y1);
                    while (wp) {
                        int y = __ffsll((long long)wp) - 1; wp &= wp - 1;
                        u64 w = __ldg(&g_occ[zb + y]) & xm;
                        if (w) {
                            int lo = __ffsll((long long)w) - 1;
                            int hi = 63 - __clzll(w);
                            scan_run((zb + y) * GD + lo, (zb + y) * GD + hi);
                        }
                    }
                } else {
                    int yl = cy - r, yr2 = cy + r;
                    if (yl >= 0) {
                        u64 w = __ldg(&g_occ[zb + yl]) & xm;
                        if (w) {
                            int lo = __ffsll((long long)w) - 1;
                            int hi = 63 - __clzll(w);
                            scan_run((zb + yl) * GD + lo, (zb + yl) * GD + hi);
                        }
                    }
                    if (yr2 <= GD - 1) {
                        u64 w = __ldg(&g_occ[zb + yr2]) & xm;
                        if (w) {
                            int lo = __ffsll((long long)w) - 1;
                            int hi = 63 - __clzll(w);
                            scan_run((zb + yr2) * GD + lo, (zb + yr2) * GD + hi);
                        }
                    }
                    int yi0 = max(yl + 1, 0), yi1 = min(yr2 - 1, GD - 1);
                    if (yi0 <= yi1) {
                        u64 ym = bitrange(yi0, yi1);
                        if (xl >= 0) {
                            u64 wc = __ldg(&g_occX[zb + xl]) & ym;
                            while (wc) {
                                int y = __ffsll((long long)wc) - 1; wc &= wc - 1;
                                int c = (zb + y) * GD + xl;
                                scan_run(c, c);
                            }
                        }
                        if (xr <= GD - 1) {
                            u64 wc = __ldg(&g_occX[zb + xr]) & ym;
                            while (wc) {
                                int y = __ffsll((long long)wc) - 1; wc &= wc - 1;
                                int c = (zb + y) * GD + xr;
                                scan_run(c, c);
                            }
                        }
                    }
                }
            }
            m = group_min();
            float rh = r * H;
            float rh2 = rh * rh;
            if (m + asq <= rh2 || rh2 > 2.0f) break;   // unscanned have d >= rh2
        }
    }

    float d = m + asq;
    float s = 0.f, c = 0.f;
    if (l == 0 && d <= 2.0f) { s = d; c = 1.f; }   // one lane per point counts

    __shared__ float ss[ST], sc[ST];
    ss[t] = s; sc[t] = c;
    __syncthreads();
    for (int o = ST / 2; o > 0; o >>= 1) {
        if (t < o) { ss[t] += ss[t + o]; sc[t] += sc[t + o]; }
        __syncthreads();
    }
    __shared__ int isLast;
    if (t == 0) {
        g_block[2 * blockIdx.x + 0] = ss[0];
        g_block[2 * blockIdx.x + 1] = sc[0];
        __threadfence();
        isLast = (atomicAdd(&g_done, 1) == SB - 1);
    }
    __syncthreads();
    if (isLast) {
        // deterministic fixed-order final reduction by the last block
        float fs = 0.f, fc = 0.f;
        for (int k = t; k < SB; k += ST) {
            fs += g_block[2 * k + 0];
            fc += g_block[2 * k + 1];
        }
        ss[t] = fs; sc[t] = fc;
        __syncthreads();
        for (int o = ST / 2; o > 0; o >>= 1) {
            if (t < o) { ss[t] += ss[t + o]; sc[t] += sc[t + o]; }
            __syncthreads();
        }
        if (t == 0) out[0] = ss[0] / sc[0];
    }
}

extern "C" void kernel_launch(void* const* d_in, const int* in_sizes, int n_in,
                              void* d_out, int out_size) {
    const float* pc0 = (const float*)d_in[0];
    const float* pc1 = (const float*)d_in[1];
    (void)in_sizes; (void)n_in; (void)out_size;

    zero_k   <<<NC / 256, 256>>>();
    count_k  <<<NPTS / 256, 256>>>(pc1, pc0);
    scan_a   <<<dim3(256, 2), 256>>>();
    scan_b   <<<3, 256>>>();
    scan_c   <<<dim3(256, 2), 256>>>();
    scatter_k<<<NPTS / 256, 256>>>(pc1, pc0);
    search_k <<<SB, ST>>>((float*)d_out);
}